// round 3
// baseline (speedup 1.0000x reference)
#include <cuda_runtime.h>

// Problem constants
#define B_    4
#define T_    2048
#define HID_  2048
#define NH_   16
#define HD_   128
#define M_    (B_ * T_)       // 8192
#define NQKV_ (3 * HID_)      // 6144

// GEMM tiling
#define BKg 16
#define PAD 132               // smem row stride (multiple of 4 for float4 alignment)

typedef unsigned long long ull_t;

// ---- packed fp32x2 helpers (FFMA2 path; ptxas never emits these on its own) ----
__device__ __forceinline__ ull_t pack2(float lo, float hi) {
    ull_t r; asm("mov.b64 %0, {%1, %2};" : "=l"(r) : "f"(lo), "f"(hi)); return r;
}
__device__ __forceinline__ ull_t rep2(float v) {
    ull_t r; asm("mov.b64 %0, {%1, %1};" : "=l"(r) : "f"(v)); return r;
}
__device__ __forceinline__ void ffma2(ull_t& d, ull_t a, ull_t b) {
    asm("fma.rn.f32x2 %0, %1, %2, %0;" : "+l"(d) : "l"(a), "l"(b));
}
__device__ __forceinline__ void mul2(ull_t& d, ull_t a) {
    asm("mul.rn.f32x2 %0, %0, %1;" : "+l"(d) : "l"(a));
}
__device__ __forceinline__ float2 unpack2(ull_t v) {
    float2 f; asm("mov.b64 {%0, %1}, %2;" : "=f"(f.x), "=f"(f.y) : "l"(v)); return f;
}

// Scratch (device globals; no allocations allowed)
__device__ float g_q[16777216];     // [B, NH, T, HD]
__device__ float g_k[16777216];
__device__ float g_v[16777216];
__device__ float g_attn[16777216];  // [B, T, HID]

// ---------------------------------------------------------------------------
// Shared 128x128x16 fp32 GEMM mainloop (FFMA2): C[row,col] = sum_k A[row,k]*Bm[col,k]
// acc2[i][jp] holds columns (2jp, 2jp+1) packed. 256 threads, 8x8 microtile.
// ---------------------------------------------------------------------------
__device__ __forceinline__ void gemm128(const float* __restrict__ A,
                                        const float* __restrict__ Bm,
                                        int K, int rowBase, int colBase,
                                        ull_t (&acc2)[8][4],
                                        float* As, float* Bs)
{
    const int tid = threadIdx.x;
    const int ty  = tid >> 4;         // 0..15
    const int tx  = tid & 15;         // 0..15
    const int lr  = tid >> 2;         // 0..63
    const int lk  = (tid & 3) << 2;   // 0,4,8,12

    for (int k0 = 0; k0 < K; k0 += BKg) {
#pragma unroll
        for (int j = 0; j < 2; ++j) {
            const int r = lr + j * 64;
            float4 va = *reinterpret_cast<const float4*>(A + (size_t)(rowBase + r) * K + k0 + lk);
            As[(lk + 0) * PAD + r] = va.x;
            As[(lk + 1) * PAD + r] = va.y;
            As[(lk + 2) * PAD + r] = va.z;
            As[(lk + 3) * PAD + r] = va.w;
            float4 vb = *reinterpret_cast<const float4*>(Bm + (size_t)(colBase + r) * K + k0 + lk);
            Bs[(lk + 0) * PAD + r] = vb.x;
            Bs[(lk + 1) * PAD + r] = vb.y;
            Bs[(lk + 2) * PAD + r] = vb.z;
            Bs[(lk + 3) * PAD + r] = vb.w;
        }
        __syncthreads();
#pragma unroll
        for (int kk = 0; kk < BKg; ++kk) {
            const float4 a0 = *reinterpret_cast<const float4*>(As + kk * PAD + ty * 4);
            const float4 a1 = *reinterpret_cast<const float4*>(As + kk * PAD + 64 + ty * 4);
            const ull_t* bp0 = reinterpret_cast<const ull_t*>(Bs + kk * PAD + tx * 4);
            const ull_t* bp1 = reinterpret_cast<const ull_t*>(Bs + kk * PAD + 64 + tx * 4);
            const ull_t b01 = bp0[0], b23 = bp0[1];
            const ull_t b45 = bp1[0], b67 = bp1[1];
            ull_t ap[8];
            ap[0] = rep2(a0.x); ap[1] = rep2(a0.y); ap[2] = rep2(a0.z); ap[3] = rep2(a0.w);
            ap[4] = rep2(a1.x); ap[5] = rep2(a1.y); ap[6] = rep2(a1.z); ap[7] = rep2(a1.w);
#pragma unroll
            for (int i = 0; i < 8; ++i) {
                ffma2(acc2[i][0], ap[i], b01);
                ffma2(acc2[i][1], ap[i], b23);
                ffma2(acc2[i][2], ap[i], b45);
                ffma2(acc2[i][3], ap[i], b67);
            }
        }
        __syncthreads();
    }
}

// ---------------------------------------------------------------------------
// Kernel 1: QKV projection + fused RoPE + scatter to [B, NH, T, HD]
// ---------------------------------------------------------------------------
__global__ void __launch_bounds__(256, 2)
qkv_rope_kernel(const float* __restrict__ x,
                const float* __restrict__ w_qkv,
                const float* __restrict__ cosb,
                const float* __restrict__ sinb)
{
    __shared__ float As[BKg * PAD];
    __shared__ float Bs[BKg * PAD];
    ull_t acc2[8][4];
#pragma unroll
    for (int i = 0; i < 8; ++i)
#pragma unroll
        for (int j = 0; j < 4; ++j) acc2[i][j] = 0ull;

    const int rowBase = blockIdx.y * 128;
    const int colBase = blockIdx.x * 128;
    gemm128(x, w_qkv, HID_, rowBase, colBase, acc2, As, Bs);

    const int ty = threadIdx.x >> 4;
    const int tx = threadIdx.x & 15;

#pragma unroll
    for (int jc = 0; jc < 2; ++jc) {
        const int col = colBase + jc * 64 + tx * 4;  // multiple of 4 -> d even
        const int s   = col >> 11;                   // 0=q, 1=k, 2=v
        const int rem = col & 2047;
        const int h   = rem >> 7;
        const int d   = rem & 127;
#pragma unroll
        for (int ic = 0; ic < 2; ++ic)
#pragma unroll
            for (int i = 0; i < 4; ++i) {
                const int m  = rowBase + ic * 64 + ty * 4 + i;
                const int bb = m >> 11;  // / T_
                const int t  = m & 2047;
                const float2 pA = unpack2(acc2[ic * 4 + i][jc * 2 + 0]);
                const float2 pB = unpack2(acc2[ic * 4 + i][jc * 2 + 1]);
                const float v0 = pA.x, v1 = pA.y, v2 = pB.x, v3 = pB.y;
                const size_t base = ((size_t)(bb * NH_ + h) * T_ + t) * HD_ + d;
                if (s == 2) {
                    float4 o4 = make_float4(v0, v1, v2, v3);
                    *reinterpret_cast<float4*>(g_v + base) = o4;
                } else {
                    const int i0 = d >> 1;
                    const float c0 = cosb[t * 64 + i0];
                    const float s0 = sinb[t * 64 + i0];
                    const float c1 = cosb[t * 64 + i0 + 1];
                    const float s1 = sinb[t * 64 + i0 + 1];
                    float4 o4;
                    o4.x = v0 * c0 - v1 * s0;
                    o4.y = v0 * s0 + v1 * c0;
                    o4.z = v2 * c1 - v3 * s1;
                    o4.w = v2 * s1 + v3 * c1;
                    float* dst = (s == 0) ? g_q : g_k;
                    *reinterpret_cast<float4*>(dst + base) = o4;
                }
            }
    }
}

// ---------------------------------------------------------------------------
// Kernel 2: flash attention, fp32 (FFMA2). One CTA = one (b,h) x 64 query rows.
// ---------------------------------------------------------------------------
#define QSTRIDE 132
#define SSTRIDE 65
#define ATTN_SMEM_FLOATS (3 * 64 * QSTRIDE + 64 * SSTRIDE + 3 * 64)
#define ATTN_SMEM_BYTES  (ATTN_SMEM_FLOATS * 4)

__global__ void attn_kernel()
{
    extern __shared__ float sm[];
    float* Qs = sm;                     // [64][132]
    float* Ks = Qs + 64 * QSTRIDE;      // [64][132]
    float* Vs = Ks + 64 * QSTRIDE;      // [64][132]
    float* Ss = Vs + 64 * QSTRIDE;      // [64][65]
    float* mb = Ss + 64 * SSTRIDE;      // row max
    float* lb = mb + 64;                // row sum
    float* ab = lb + 64;                // row alpha

    const int tid = threadIdx.x;
    const int ty = tid >> 4;            // 0..15
    const int tx = tid & 15;            // 0..15
    const int bh = blockIdx.y;
    const int qBase = blockIdx.x * 64;

    const float* __restrict__ Qg = g_q + (size_t)bh * T_ * HD_;
    const float* __restrict__ Kg = g_k + (size_t)bh * T_ * HD_;
    const float* __restrict__ Vg = g_v + (size_t)bh * T_ * HD_;

    const float scale = 0.08838834764831845f;  // 1/sqrt(128)

    // Load Q tile (scaled)
    {
        const int r0 = tid >> 5;             // 0..7
        const int kc = (tid & 31) << 2;      // 0..124
#pragma unroll
        for (int it = 0; it < 8; ++it) {
            const int row = r0 + it * 8;
            float4 v = *reinterpret_cast<const float4*>(Qg + (size_t)(qBase + row) * HD_ + kc);
            Qs[row * QSTRIDE + kc + 0] = v.x * scale;
            Qs[row * QSTRIDE + kc + 1] = v.y * scale;
            Qs[row * QSTRIDE + kc + 2] = v.z * scale;
            Qs[row * QSTRIDE + kc + 3] = v.w * scale;
        }
    }
    if (tid < 64) { mb[tid] = -1e30f; lb[tid] = 0.f; }

    // O accumulator: pairs over columns. oacc[i][jp] = (O[i][2jp], O[i][2jp+1])
    ull_t oacc[4][4];
#pragma unroll
    for (int i = 0; i < 4; ++i)
#pragma unroll
        for (int j = 0; j < 4; ++j) oacc[i][j] = 0ull;

    for (int n0 = 0; n0 < T_; n0 += 64) {
        __syncthreads();  // prior tile's reads of Vs/Ss done (covers Q load on iter 0)

        // Load K, V tiles
        {
            const int r0 = tid >> 5;
            const int kc = (tid & 31) << 2;
#pragma unroll
            for (int it = 0; it < 8; ++it) {
                const int row = r0 + it * 8;
                float4 kv = *reinterpret_cast<const float4*>(Kg + (size_t)(n0 + row) * HD_ + kc);
                Ks[row * QSTRIDE + kc + 0] = kv.x;
                Ks[row * QSTRIDE + kc + 1] = kv.y;
                Ks[row * QSTRIDE + kc + 2] = kv.z;
                Ks[row * QSTRIDE + kc + 3] = kv.w;
                float4 vv = *reinterpret_cast<const float4*>(Vg + (size_t)(n0 + row) * HD_ + kc);
                Vs[row * QSTRIDE + kc + 0] = vv.x;
                Vs[row * QSTRIDE + kc + 1] = vv.y;
                Vs[row * QSTRIDE + kc + 2] = vv.z;
                Vs[row * QSTRIDE + kc + 3] = vv.w;
            }
        }
        __syncthreads();

        // S = Q @ K^T : pair over kd (both operands contiguous LDS.64, no movs)
        {
            ull_t sacc[4][4];
#pragma unroll
            for (int i = 0; i < 4; ++i)
#pragma unroll
                for (int j = 0; j < 4; ++j) sacc[i][j] = 0ull;

#pragma unroll 4
            for (int kd = 0; kd < HD_; kd += 2) {
                ull_t qv[4], kv[4];
#pragma unroll
                for (int i = 0; i < 4; ++i)
                    qv[i] = *reinterpret_cast<const ull_t*>(Qs + (4 * ty + i) * QSTRIDE + kd);
#pragma unroll
                for (int j = 0; j < 4; ++j)
                    kv[j] = *reinterpret_cast<const ull_t*>(Ks + (4 * tx + j) * QSTRIDE + kd);
#pragma unroll
                for (int i = 0; i < 4; ++i)
#pragma unroll
                    for (int j = 0; j < 4; ++j)
                        ffma2(sacc[i][j], qv[i], kv[j]);
            }
#pragma unroll
            for (int i = 0; i < 4; ++i)
#pragma unroll
                for (int j = 0; j < 4; ++j) {
                    const float2 p = unpack2(sacc[i][j]);
                    Ss[(4 * ty + i) * SSTRIDE + 4 * tx + j] = p.x + p.y;
                }
        }
        __syncthreads();

        // Online softmax: 4 threads per row, shuffle-reduce within 4-lane group
        {
            const int r   = tid >> 2;
            const int sub = tid & 3;
            float* row = Ss + r * SSTRIDE;
            const float mOld = mb[r];
            float mNew = mOld;
#pragma unroll
            for (int c = 0; c < 16; ++c) mNew = fmaxf(mNew, row[sub * 16 + c]);
            mNew = fmaxf(mNew, __shfl_xor_sync(0xFFFFFFFFu, mNew, 1));
            mNew = fmaxf(mNew, __shfl_xor_sync(0xFFFFFFFFu, mNew, 2));
            float l = 0.f;
#pragma unroll
            for (int c = 0; c < 16; ++c) {
                const float p = __expf(row[sub * 16 + c] - mNew);
                row[sub * 16 + c] = p;
                l += p;
            }
            l += __shfl_xor_sync(0xFFFFFFFFu, l, 1);
            l += __shfl_xor_sync(0xFFFFFFFFu, l, 2);
            if (sub == 0) {
                const float alpha = __expf(mOld - mNew);
                mb[r] = mNew;
                lb[r] = lb[r] * alpha + l;
                ab[r] = alpha;
            }
        }
        __syncthreads();

        // Rescale accumulators, then O += P @ V  (pairs over output columns)
        {
            ull_t al[4];
#pragma unroll
            for (int i = 0; i < 4; ++i) al[i] = rep2(ab[4 * ty + i]);
#pragma unroll
            for (int i = 0; i < 4; ++i)
#pragma unroll
                for (int j = 0; j < 4; ++j) mul2(oacc[i][j], al[i]);

#pragma unroll 4
            for (int kc = 0; kc < 64; ++kc) {
                ull_t prep[4];
#pragma unroll
                for (int i = 0; i < 4; ++i)
                    prep[i] = rep2(Ss[(4 * ty + i) * SSTRIDE + kc]);
                const ull_t* vp0 = reinterpret_cast<const ull_t*>(Vs + kc * QSTRIDE + 4 * tx);
                const ull_t* vp1 = reinterpret_cast<const ull_t*>(Vs + kc * QSTRIDE + 64 + 4 * tx);
                const ull_t v01 = vp0[0], v23 = vp0[1];
                const ull_t v45 = vp1[0], v67 = vp1[1];
#pragma unroll
                for (int i = 0; i < 4; ++i) {
                    ffma2(oacc[i][0], prep[i], v01);
                    ffma2(oacc[i][1], prep[i], v23);
                    ffma2(oacc[i][2], prep[i], v45);
                    ffma2(oacc[i][3], prep[i], v67);
                }
            }
        }
    }

    // Write to g_attn[b, t, h*128 + d]
    const int b = bh / NH_;
    const int h = bh % NH_;
#pragma unroll
    for (int i = 0; i < 4; ++i) {
        const int row = 4 * ty + i;
        const float inv = 1.f / lb[row];
        const int t = qBase + row;
        float* dst = g_attn + ((size_t)(b * T_ + t)) * HID_ + h * HD_;
        const float2 p0 = unpack2(oacc[i][0]);
        const float2 p1 = unpack2(oacc[i][1]);
        const float2 p2 = unpack2(oacc[i][2]);
        const float2 p3 = unpack2(oacc[i][3]);
        float4 o0 = make_float4(p0.x * inv, p0.y * inv, p1.x * inv, p1.y * inv);
        float4 o1 = make_float4(p2.x * inv, p2.y * inv, p3.x * inv, p3.y * inv);
        *reinterpret_cast<float4*>(dst + 4 * tx) = o0;
        *reinterpret_cast<float4*>(dst + 64 + 4 * tx) = o1;
    }
}

// ---------------------------------------------------------------------------
// Kernel 3: output projection + bias
// ---------------------------------------------------------------------------
__global__ void __launch_bounds__(256, 2)
proj_kernel(const float* __restrict__ w_proj,
            const float* __restrict__ bias,
            float* __restrict__ out)
{
    __shared__ float As[BKg * PAD];
    __shared__ float Bs[BKg * PAD];
    ull_t acc2[8][4];
#pragma unroll
    for (int i = 0; i < 8; ++i)
#pragma unroll
        for (int j = 0; j < 4; ++j) acc2[i][j] = 0ull;

    const int rowBase = blockIdx.y * 128;
    const int colBase = blockIdx.x * 128;
    gemm128(g_attn, w_proj, HID_, rowBase, colBase, acc2, As, Bs);

    const int ty = threadIdx.x >> 4;
    const int tx = threadIdx.x & 15;
#pragma unroll
    for (int jc = 0; jc < 2; ++jc) {
        const int col = colBase + jc * 64 + tx * 4;
        const float b0 = bias[col + 0];
        const float b1 = bias[col + 1];
        const float b2 = bias[col + 2];
        const float b3 = bias[col + 3];
#pragma unroll
        for (int ic = 0; ic < 2; ++ic)
#pragma unroll
            for (int i = 0; i < 4; ++i) {
                const int m = rowBase + ic * 64 + ty * 4 + i;
                const float2 pA = unpack2(acc2[ic * 4 + i][jc * 2 + 0]);
                const float2 pB = unpack2(acc2[ic * 4 + i][jc * 2 + 1]);
                float4 o4;
                o4.x = pA.x + b0;
                o4.y = pA.y + b1;
                o4.z = pB.x + b2;
                o4.w = pB.y + b3;
                *reinterpret_cast<float4*>(out + (size_t)m * HID_ + col) = o4;
            }
    }
}

// ---------------------------------------------------------------------------
extern "C" void kernel_launch(void* const* d_in, const int* in_sizes, int n_in,
                              void* d_out, int out_size)
{
    const float* x      = (const float*)d_in[0];
    const float* w_qkv  = (const float*)d_in[1];
    const float* w_proj = (const float*)d_in[2];
    const float* b_proj = (const float*)d_in[3];
    const float* cosb   = (const float*)d_in[4];
    const float* sinb   = (const float*)d_in[5];
    float* out = (float*)d_out;

    // 1) QKV GEMM + RoPE scatter
    qkv_rope_kernel<<<dim3(NQKV_ / 128, M_ / 128), 256>>>(x, w_qkv, cosb, sinb);

    // 2) Flash attention
    cudaFuncSetAttribute(attn_kernel, cudaFuncAttributeMaxDynamicSharedMemorySize,
                         ATTN_SMEM_BYTES);
    attn_kernel<<<dim3(T_ / 64, B_ * NH_), 256, ATTN_SMEM_BYTES>>>();

    // 3) Output projection + bias
    proj_kernel<<<dim3(HID_ / 128, M_ / 128), 256>>>(w_proj, b_proj, out);
}

// round 13
// speedup vs baseline: 2.0315x; 2.0315x over previous
#include <cuda_runtime.h>
#include <cuda_bf16.h>

typedef unsigned int u32;
typedef unsigned long long u64;

// Problem constants
#define B_    4
#define T_    2048
#define HID_  2048
#define NH_   16
#define HD_   128
#define M_    (B_ * T_)       // 8192
#define NQKV_ (3 * HID_)      // 6144
#define KDIM  2048

// ---------------------------------------------------------------------------
// Scratch (device globals; no allocations allowed)
// ---------------------------------------------------------------------------
__device__ float g_q[16777216];     // [B, NH, T, HD]
__device__ float g_k[16777216];
__device__ float g_v[16777216];
__device__ float g_attn[16777216];  // [B, T, HID]
__device__ __nv_bfloat16 gx_hi[16777216],  gx_lo[16777216];   // x split
__device__ __nv_bfloat16 gw1_hi[12582912], gw1_lo[12582912];  // w_qkv split
__device__ __nv_bfloat16 gw2_hi[4194304],  gw2_lo[4194304];   // w_proj split
__device__ __nv_bfloat16 ga_hi[16777216],  ga_lo[16777216];   // attn out split

// ---------------------------------------------------------------------------
// PTX helpers — BASE-target only (no 'a'-suffix features; ptxas targets sm_103)
// ---------------------------------------------------------------------------
__device__ __forceinline__ u32 s2u(const void* p) {
    u32 a;
    asm("{ .reg .u64 t; cvta.to.shared.u64 t, %1; cvt.u32.u64 %0, t; }"
        : "=r"(a) : "l"(p));
    return a;
}

#define CP_ASYNC16(dst, src) \
    asm volatile("cp.async.cg.shared.global [%0], [%1], 16;" \
                 :: "r"(dst), "l"(src) : "memory")
#define CP_COMMIT() asm volatile("cp.async.commit_group;" ::: "memory")
#define CP_WAIT1()  asm volatile("cp.async.wait_group 1;" ::: "memory")

#define LDSM4(R, addr) \
    asm volatile("ldmatrix.sync.aligned.m8n8.x4.shared.b16 {%0,%1,%2,%3}, [%4];" \
        : "=r"((R)[0]), "=r"((R)[1]), "=r"((R)[2]), "=r"((R)[3]) : "r"(addr))

#define MMA_BF16(c, a, b) \
    asm volatile("mma.sync.aligned.m16n8k16.row.col.f32.bf16.bf16.f32 " \
        "{%0,%1,%2,%3}, {%4,%5,%6,%7}, {%8,%9}, {%0,%1,%2,%3};" \
        : "+f"((c)[0]), "+f"((c)[1]), "+f"((c)[2]), "+f"((c)[3]) \
        : "r"((a)[0]), "r"((a)[1]), "r"((a)[2]), "r"((a)[3]), \
          "r"((b)[0]), "r"((b)[1]))

// ---------------------------------------------------------------------------
// Kernel: fp32 -> bf16 hi/lo split. which: 0=x, 1=w_qkv, 2=w_proj, 3=g_attn
// ---------------------------------------------------------------------------
__global__ void split_kernel(const float* __restrict__ src_in, int which, int n4)
{
    const int i = blockIdx.x * blockDim.x + threadIdx.x;
    if (i >= n4) return;
    const float* src = src_in;
    __nv_bfloat16 *hi, *lo;
    if      (which == 0) { hi = gx_hi;  lo = gx_lo;  }
    else if (which == 1) { hi = gw1_hi; lo = gw1_lo; }
    else if (which == 2) { hi = gw2_hi; lo = gw2_lo; }
    else                 { hi = ga_hi;  lo = ga_lo;  src = g_attn; }

    const float4 v = reinterpret_cast<const float4*>(src)[i];
    const __nv_bfloat16 h0 = __float2bfloat16(v.x);
    const __nv_bfloat16 h1 = __float2bfloat16(v.y);
    const __nv_bfloat16 h2 = __float2bfloat16(v.z);
    const __nv_bfloat16 h3 = __float2bfloat16(v.w);
    const __nv_bfloat16 l0 = __float2bfloat16(v.x - __bfloat162float(h0));
    const __nv_bfloat16 l1 = __float2bfloat16(v.y - __bfloat162float(h1));
    const __nv_bfloat16 l2 = __float2bfloat16(v.z - __bfloat162float(h2));
    const __nv_bfloat16 l3 = __float2bfloat16(v.w - __bfloat162float(h3));
    __nv_bfloat162 H01; H01.x = h0; H01.y = h1;
    __nv_bfloat162 H23; H23.x = h2; H23.y = h3;
    __nv_bfloat162 L01; L01.x = l0; L01.y = l1;
    __nv_bfloat162 L23; L23.x = l2; L23.y = l3;
    reinterpret_cast<__nv_bfloat162*>(hi)[2 * i + 0] = H01;
    reinterpret_cast<__nv_bfloat162*>(hi)[2 * i + 1] = H23;
    reinterpret_cast<__nv_bfloat162*>(lo)[2 * i + 0] = L01;
    reinterpret_cast<__nv_bfloat162*>(lo)[2 * i + 1] = L23;
}

// ---------------------------------------------------------------------------
// HMMA GEMM: C[128,128 tile] = A[M,K] * B[N,K]^T with bf16x3 compensation.
// mma.sync.m16n8k16 bf16, cp.async double-buffered smem, 256 threads.
// Warp grid 4(M)x2(N): warp tile M32 x N64.
// mode 0: A=x split, B=w_qkv split, epilogue = RoPE + scatter to g_q/g_k/g_v
// mode 1: A=attn split, B=w_proj split, epilogue = +bias -> out
// ---------------------------------------------------------------------------
#define TK 64
#define NITER (KDIM / TK)        // 32
#define ROWB 144                 // smem row stride bytes (72 bf16, pad 8)
#define TILE_B (128 * ROWB)      // 18432 bytes per operand tile
#define BUF_B (4 * TILE_B)       // Ahi,Alo,Bhi,Blo = 73728
#define GEMM_SMEM (2 * BUF_B)    // 147456

__device__ __forceinline__ void stage_load(
    u32 sbuf, const __nv_bfloat16* __restrict__ Ahi,
    const __nv_bfloat16* __restrict__ Alo,
    const __nv_bfloat16* __restrict__ Bhi,
    const __nv_bfloat16* __restrict__ Blo,
    int rowBase, int colBase, int k0, int tid)
{
#pragma unroll
    for (int i = 0; i < 16; ++i) {
        const int tile = i >> 2;                       // 0..3 (static)
        const int row  = (i & 3) * 32 + (tid >> 3);    // 0..127
        const int ch   = tid & 7;                      // 16B chunk in row
        const __nv_bfloat16* srcb =
            (tile == 0) ? Ahi : (tile == 1) ? Alo : (tile == 2) ? Bhi : Blo;
        const int gr = ((tile < 2) ? rowBase : colBase) + row;
        const __nv_bfloat16* g = srcb + (size_t)gr * KDIM + k0 + ch * 8;
        const u32 dst = sbuf + tile * TILE_B + row * ROWB + ch * 16;
        CP_ASYNC16(dst, g);
    }
}

__global__ void __launch_bounds__(256, 1)
hmma_gemm_kernel(const float* __restrict__ cosb, const float* __restrict__ sinb,
                 const float* __restrict__ bias, float* __restrict__ out, int mode)
{
    extern __shared__ char smc[];
    const u32 smu = s2u(smc);
    const int tid  = threadIdx.x;
    const int lane = tid & 31;
    const int wid  = tid >> 5;
    const int warpM = wid & 3;       // 0..3 -> M offset *32
    const int warpN = wid >> 2;      // 0..1 -> N offset *64

    const __nv_bfloat16 *Ahi, *Alo, *Bhi, *Blo;
    if (mode == 0) { Ahi = gx_hi; Alo = gx_lo; Bhi = gw1_hi; Blo = gw1_lo; }
    else           { Ahi = ga_hi; Alo = ga_lo; Bhi = gw2_hi; Blo = gw2_lo; }

    const int rowBase = blockIdx.y * 128;
    const int colBase = blockIdx.x * 128;

    float acc[2][8][4];
#pragma unroll
    for (int mf = 0; mf < 2; ++mf)
#pragma unroll
        for (int nf = 0; nf < 8; ++nf)
#pragma unroll
            for (int r = 0; r < 4; ++r) acc[mf][nf][r] = 0.f;

    // Precomputed smem fragment address components
    const int arow = warpM * 32 + (lane & 15);
    const u32 aoff = arow * ROWB + ((lane >> 4) * 8) * 2;
    const int brow = warpN * 64 + ((lane >> 4) << 3) + (lane & 7);
    const u32 boff = brow * ROWB + (((lane >> 3) & 1) * 8) * 2;

    // Prologue: stage k-chunk 0 into buffer 0
    stage_load(smu, Ahi, Alo, Bhi, Blo, rowBase, colBase, 0, tid);
    CP_COMMIT();

    for (int it = 0; it < NITER; ++it) {
        if (it + 1 < NITER)
            stage_load(smu + ((it + 1) & 1) * BUF_B, Ahi, Alo, Bhi, Blo,
                       rowBase, colBase, (it + 1) * TK, tid);
        CP_COMMIT();
        CP_WAIT1();
        __syncthreads();

        const u32 ab = smu + (it & 1) * BUF_B;
#pragma unroll
        for (int ks = 0; ks < 4; ++ks) {
            const u32 kb = ks * 32;   // 16 bf16 = 32 bytes
            u32 a_hi[8], a_lo[8], b_hi[16], b_lo[16];
#pragma unroll
            for (int mf = 0; mf < 2; ++mf) {
                LDSM4(&a_hi[mf * 4], ab + 0 * TILE_B + aoff + mf * 16 * ROWB + kb);
                LDSM4(&a_lo[mf * 4], ab + 1 * TILE_B + aoff + mf * 16 * ROWB + kb);
            }
#pragma unroll
            for (int np = 0; np < 4; ++np) {
                LDSM4(&b_hi[np * 4], ab + 2 * TILE_B + boff + np * 16 * ROWB + kb);
                LDSM4(&b_lo[np * 4], ab + 3 * TILE_B + boff + np * 16 * ROWB + kb);
            }
#pragma unroll
            for (int nf = 0; nf < 8; ++nf)
#pragma unroll
                for (int mf = 0; mf < 2; ++mf) {
                    MMA_BF16(acc[mf][nf], &a_hi[mf * 4], &b_hi[nf * 2]);
                    MMA_BF16(acc[mf][nf], &a_hi[mf * 4], &b_lo[nf * 2]);
                    MMA_BF16(acc[mf][nf], &a_lo[mf * 4], &b_hi[nf * 2]);
                }
        }
        __syncthreads();
    }

    // ---------------- Epilogue ----------------
    // acc regs: c0,c1 -> row r, cols c,c+1 ; c2,c3 -> row r+8.
    // r = lane>>2, c = 2*(lane&3). Even/odd column pairs are thread-local.
    const int lane4 = lane >> 2;
    const int lanec = (lane & 3) * 2;

#pragma unroll
    for (int mf = 0; mf < 2; ++mf)
#pragma unroll
        for (int half = 0; half < 2; ++half) {
            const int m = rowBase + warpM * 32 + mf * 16 + lane4 + half * 8;
            if (mode == 0) {
                const int b = m >> 11;
                const int t = m & 2047;
#pragma unroll
                for (int nf = 0; nf < 8; ++nf) {
                    const int col = colBase + warpN * 64 + nf * 8 + lanec;
                    const float e = acc[mf][nf][half * 2 + 0];
                    const float o = acc[mf][nf][half * 2 + 1];
                    const int s = col >> 11;
                    const int h = (col >> 7) & 15;
                    const int d = col & 127;
                    float* dstp = (s == 0) ? g_q : ((s == 1) ? g_k : g_v);
                    const size_t base =
                        (((size_t)(b * NH_ + h)) * T_ + t) * HD_ + d;
                    float2 o2;
                    if (s == 2) {
                        o2.x = e; o2.y = o;
                    } else {
                        const int i0 = d >> 1;
                        const float c  = cosb[t * 64 + i0];
                        const float sn = sinb[t * 64 + i0];
                        o2.x = e * c - o * sn;
                        o2.y = e * sn + o * c;
                    }
                    *reinterpret_cast<float2*>(dstp + base) = o2;
                }
            } else {
#pragma unroll
                for (int nf = 0; nf < 8; ++nf) {
                    const int col = colBase + warpN * 64 + nf * 8 + lanec;
                    float2 o2;
                    o2.x = acc[mf][nf][half * 2 + 0] + bias[col];
                    o2.y = acc[mf][nf][half * 2 + 1] + bias[col + 1];
                    *reinterpret_cast<float2*>(out + (size_t)m * HID_ + col) = o2;
                }
            }
        }
}

// ---------------------------------------------------------------------------
// Kernel 2: flash attention, fp32 scalar (round-2 proven version).
// ---------------------------------------------------------------------------
#define QSTRIDE 132
#define SSTRIDE 65
#define ATTN_SMEM_FLOATS (3 * 64 * QSTRIDE + 64 * SSTRIDE + 3 * 64)
#define ATTN_SMEM_BYTES  (ATTN_SMEM_FLOATS * 4)

__global__ void attn_kernel()
{
    extern __shared__ float sm[];
    float* Qs = sm;                     // [64][132]
    float* Ks = Qs + 64 * QSTRIDE;      // [64][132]
    float* Vs = Ks + 64 * QSTRIDE;      // [64][132]
    float* Ss = Vs + 64 * QSTRIDE;      // [64][65]
    float* mb = Ss + 64 * SSTRIDE;      // row max
    float* lb = mb + 64;                // row sum
    float* ab = lb + 64;                // row alpha

    const int tid = threadIdx.x;
    const int ty = tid >> 4;
    const int tx = tid & 15;
    const int bh = blockIdx.y;
    const int qBase = blockIdx.x * 64;

    const float* __restrict__ Qg = g_q + (size_t)bh * T_ * HD_;
    const float* __restrict__ Kg = g_k + (size_t)bh * T_ * HD_;
    const float* __restrict__ Vg = g_v + (size_t)bh * T_ * HD_;

    const float scale = 0.08838834764831845f;  // 1/sqrt(128)

    {
        const int r0 = tid >> 5;
        const int kc = (tid & 31) << 2;
#pragma unroll
        for (int it = 0; it < 8; ++it) {
            const int row = r0 + it * 8;
            float4 v = *reinterpret_cast<const float4*>(Qg + (size_t)(qBase + row) * HD_ + kc);
            Qs[row * QSTRIDE + kc + 0] = v.x * scale;
            Qs[row * QSTRIDE + kc + 1] = v.y * scale;
            Qs[row * QSTRIDE + kc + 2] = v.z * scale;
            Qs[row * QSTRIDE + kc + 3] = v.w * scale;
        }
    }
    if (tid < 64) { mb[tid] = -1e30f; lb[tid] = 0.f; }

    float oa[4][8];
#pragma unroll
    for (int i = 0; i < 4; ++i)
#pragma unroll
        for (int j = 0; j < 8; ++j) oa[i][j] = 0.f;

    for (int n0 = 0; n0 < T_; n0 += 64) {
        __syncthreads();
        {
            const int r0 = tid >> 5;
            const int kc = (tid & 31) << 2;
#pragma unroll
            for (int it = 0; it < 8; ++it) {
                const int row = r0 + it * 8;
                float4 kv = *reinterpret_cast<const float4*>(Kg + (size_t)(n0 + row) * HD_ + kc);
                Ks[row * QSTRIDE + kc + 0] = kv.x;
                Ks[row * QSTRIDE + kc + 1] = kv.y;
                Ks[row * QSTRIDE + kc + 2] = kv.z;
                Ks[row * QSTRIDE + kc + 3] = kv.w;
                float4 vv = *reinterpret_cast<const float4*>(Vg + (size_t)(n0 + row) * HD_ + kc);
                Vs[row * QSTRIDE + kc + 0] = vv.x;
                Vs[row * QSTRIDE + kc + 1] = vv.y;
                Vs[row * QSTRIDE + kc + 2] = vv.z;
                Vs[row * QSTRIDE + kc + 3] = vv.w;
            }
        }
        __syncthreads();

        float sa[4][4];
#pragma unroll
        for (int i = 0; i < 4; ++i)
#pragma unroll
            for (int j = 0; j < 4; ++j) sa[i][j] = 0.f;

#pragma unroll 4
        for (int kd = 0; kd < HD_; ++kd) {
            float qv[4], kv[4];
#pragma unroll
            for (int i = 0; i < 4; ++i) qv[i] = Qs[(4 * ty + i) * QSTRIDE + kd];
#pragma unroll
            for (int j = 0; j < 4; ++j) kv[j] = Ks[(4 * tx + j) * QSTRIDE + kd];
#pragma unroll
            for (int i = 0; i < 4; ++i)
#pragma unroll
                for (int j = 0; j < 4; ++j) sa[i][j] += qv[i] * kv[j];
        }
#pragma unroll
        for (int i = 0; i < 4; ++i)
#pragma unroll
            for (int j = 0; j < 4; ++j)
                Ss[(4 * ty + i) * SSTRIDE + 4 * tx + j] = sa[i][j];
        __syncthreads();

        if (tid < 64) {
            float* row = Ss + tid * SSTRIDE;
            const float mOld = mb[tid];
            float mNew = mOld;
#pragma unroll 8
            for (int c = 0; c < 64; ++c) mNew = fmaxf(mNew, row[c]);
            const float alpha = __expf(mOld - mNew);
            float l = lb[tid] * alpha;
#pragma unroll 8
            for (int c = 0; c < 64; ++c) {
                const float p = __expf(row[c] - mNew);
                row[c] = p;
                l += p;
            }
            mb[tid] = mNew;
            lb[tid] = l;
            ab[tid] = alpha;
        }
        __syncthreads();

        float al[4];
#pragma unroll
        for (int i = 0; i < 4; ++i) al[i] = ab[4 * ty + i];
#pragma unroll
        for (int i = 0; i < 4; ++i)
#pragma unroll
            for (int j = 0; j < 8; ++j) oa[i][j] *= al[i];

#pragma unroll 4
        for (int kc = 0; kc < 64; ++kc) {
            float pv[4];
#pragma unroll
            for (int i = 0; i < 4; ++i) pv[i] = Ss[(4 * ty + i) * SSTRIDE + kc];
            float4 v0 = *reinterpret_cast<const float4*>(Vs + kc * QSTRIDE + 4 * tx);
            float4 v1 = *reinterpret_cast<const float4*>(Vs + kc * QSTRIDE + 64 + 4 * tx);
#pragma unroll
            for (int i = 0; i < 4; ++i) {
                oa[i][0] += pv[i] * v0.x;
                oa[i][1] += pv[i] * v0.y;
                oa[i][2] += pv[i] * v0.z;
                oa[i][3] += pv[i] * v0.w;
                oa[i][4] += pv[i] * v1.x;
                oa[i][5] += pv[i] * v1.y;
                oa[i][6] += pv[i] * v1.z;
                oa[i][7] += pv[i] * v1.w;
            }
        }
    }

    const int b = bh / NH_;
    const int h = bh % NH_;
#pragma unroll
    for (int i = 0; i < 4; ++i) {
        const int row = 4 * ty + i;
        const float inv = 1.f / lb[row];
        const int t = qBase + row;
        float* dst = g_attn + ((size_t)(b * T_ + t)) * HID_ + h * HD_;
        float4 o0 = make_float4(oa[i][0] * inv, oa[i][1] * inv, oa[i][2] * inv, oa[i][3] * inv);
        float4 o1 = make_float4(oa[i][4] * inv, oa[i][5] * inv, oa[i][6] * inv, oa[i][7] * inv);
        *reinterpret_cast<float4*>(dst + 4 * tx) = o0;
        *reinterpret_cast<float4*>(dst + 64 + 4 * tx) = o1;
    }
}

// ---------------------------------------------------------------------------
extern "C" void kernel_launch(void* const* d_in, const int* in_sizes, int n_in,
                              void* d_out, int out_size)
{
    const float* x      = (const float*)d_in[0];
    const float* w_qkv  = (const float*)d_in[1];
    const float* w_proj = (const float*)d_in[2];
    const float* b_proj = (const float*)d_in[3];
    const float* cosb   = (const float*)d_in[4];
    const float* sinb   = (const float*)d_in[5];
    float* out = (float*)d_out;

    cudaFuncSetAttribute(hmma_gemm_kernel, cudaFuncAttributeMaxDynamicSharedMemorySize,
                         GEMM_SMEM);
    cudaFuncSetAttribute(attn_kernel, cudaFuncAttributeMaxDynamicSharedMemorySize,
                         ATTN_SMEM_BYTES);

    // 1) bf16 hi/lo splits of x, w_qkv, w_proj
    split_kernel<<<(M_ * HID_ / 4 + 255) / 256, 256>>>(x, 0, M_ * HID_ / 4);
    split_kernel<<<(NQKV_ * HID_ / 4 + 255) / 256, 256>>>(w_qkv, 1, NQKV_ * HID_ / 4);
    split_kernel<<<(HID_ * HID_ / 4 + 255) / 256, 256>>>(w_proj, 2, HID_ * HID_ / 4);

    // 2) QKV projection (HMMA bf16x3) + fused RoPE scatter
    hmma_gemm_kernel<<<dim3(NQKV_ / 128, M_ / 128), 256, GEMM_SMEM>>>(
        cosb, sinb, nullptr, nullptr, 0);

    // 3) Flash attention (fp32 scalar)
    attn_kernel<<<dim3(T_ / 64, B_ * NH_), 256, ATTN_SMEM_BYTES>>>();

    // 4) Split attention output, then output projection (HMMA bf16x3) + bias
    split_kernel<<<(M_ * HID_ / 4 + 255) / 256, 256>>>(nullptr, 3, M_ * HID_ / 4);
    hmma_gemm_kernel<<<dim3(HID_ / 128, M_ / 128), 256, GEMM_SMEM>>>(
        nullptr, nullptr, b_proj, out, 1);
}

// round 14
// speedup vs baseline: 5.4281x; 2.6720x over previous
#include <cuda_runtime.h>
#include <cuda_bf16.h>

typedef unsigned int u32;
typedef unsigned long long u64;

// Problem constants
#define B_    4
#define T_    2048
#define HID_  2048
#define NH_   16
#define HD_   128
#define M_    (B_ * T_)       // 8192
#define NQKV_ (3 * HID_)      // 6144
#define KDIM  2048

// ---------------------------------------------------------------------------
// Scratch (device globals; no allocations allowed)
// ---------------------------------------------------------------------------
__device__ __nv_bfloat16 gx_hi[16777216],  gx_lo[16777216];   // x split
__device__ __nv_bfloat16 gw1_hi[12582912], gw1_lo[12582912];  // w_qkv split
__device__ __nv_bfloat16 gw2_hi[4194304],  gw2_lo[4194304];   // w_proj split
__device__ __nv_bfloat16 ga_hi[16777216],  ga_lo[16777216];   // attn out split
__device__ __nv_bfloat16 gq_hi[16777216],  gq_lo[16777216];   // q (RoPE'd) split
__device__ __nv_bfloat16 gk_hi[16777216],  gk_lo[16777216];   // k (RoPE'd) split
__device__ __nv_bfloat16 gv_hi[16777216],  gv_lo[16777216];   // v split

// ---------------------------------------------------------------------------
// PTX helpers — BASE-target only (no 'a'-suffix features; ptxas targets sm_103)
// ---------------------------------------------------------------------------
__device__ __forceinline__ u32 s2u(const void* p) {
    u32 a;
    asm("{ .reg .u64 t; cvta.to.shared.u64 t, %1; cvt.u32.u64 %0, t; }"
        : "=r"(a) : "l"(p));
    return a;
}

#define CP_ASYNC16(dst, src) \
    asm volatile("cp.async.cg.shared.global [%0], [%1], 16;" \
                 :: "r"(dst), "l"(src) : "memory")
#define CP_COMMIT() asm volatile("cp.async.commit_group;" ::: "memory")
#define CP_WAIT1()  asm volatile("cp.async.wait_group 1;" ::: "memory")

#define LDSM4(R, addr) \
    asm volatile("ldmatrix.sync.aligned.m8n8.x4.shared.b16 {%0,%1,%2,%3}, [%4];" \
        : "=r"((R)[0]), "=r"((R)[1]), "=r"((R)[2]), "=r"((R)[3]) : "r"(addr))

#define LDSM4T(R, addr) \
    asm volatile("ldmatrix.sync.aligned.m8n8.x4.trans.shared.b16 {%0,%1,%2,%3}, [%4];" \
        : "=r"((R)[0]), "=r"((R)[1]), "=r"((R)[2]), "=r"((R)[3]) : "r"(addr))

#define MMA_BF16(c, a, b) \
    asm volatile("mma.sync.aligned.m16n8k16.row.col.f32.bf16.bf16.f32 " \
        "{%0,%1,%2,%3}, {%4,%5,%6,%7}, {%8,%9}, {%0,%1,%2,%3};" \
        : "+f"((c)[0]), "+f"((c)[1]), "+f"((c)[2]), "+f"((c)[3]) \
        : "r"((a)[0]), "r"((a)[1]), "r"((a)[2]), "r"((a)[3]), \
          "r"((b)[0]), "r"((b)[1]))

__device__ __forceinline__ u32 pack_hl(float a, float b, u32& lo_out) {
    const __nv_bfloat16 ha = __float2bfloat16(a);
    const __nv_bfloat16 hb = __float2bfloat16(b);
    const __nv_bfloat16 la = __float2bfloat16(a - __bfloat162float(ha));
    const __nv_bfloat16 lb = __float2bfloat16(b - __bfloat162float(hb));
    __nv_bfloat162 H; H.x = ha; H.y = hb;
    __nv_bfloat162 L; L.x = la; L.y = lb;
    lo_out = *reinterpret_cast<u32*>(&L);
    return *reinterpret_cast<u32*>(&H);
}

// ---------------------------------------------------------------------------
// Kernel: fp32 -> bf16 hi/lo split. which: 0=x, 1=w_qkv, 2=w_proj
// ---------------------------------------------------------------------------
__global__ void split_kernel(const float* __restrict__ src, int which, int n4)
{
    const int i = blockIdx.x * blockDim.x + threadIdx.x;
    if (i >= n4) return;
    __nv_bfloat16 *hi, *lo;
    if      (which == 0) { hi = gx_hi;  lo = gx_lo;  }
    else if (which == 1) { hi = gw1_hi; lo = gw1_lo; }
    else                 { hi = gw2_hi; lo = gw2_lo; }

    const float4 v = reinterpret_cast<const float4*>(src)[i];
    u32 l01, l23;
    const u32 h01 = pack_hl(v.x, v.y, l01);
    const u32 h23 = pack_hl(v.z, v.w, l23);
    reinterpret_cast<u32*>(hi)[2 * i + 0] = h01;
    reinterpret_cast<u32*>(hi)[2 * i + 1] = h23;
    reinterpret_cast<u32*>(lo)[2 * i + 0] = l01;
    reinterpret_cast<u32*>(lo)[2 * i + 1] = l23;
}

// ---------------------------------------------------------------------------
// HMMA GEMM: C[128,128 tile] = A[M,K] * B[N,K]^T with bf16x3 compensation.
// mode 0: A=x split, B=w_qkv split, epilogue = RoPE + hi/lo split scatter
// mode 1: A=attn split, B=w_proj split, epilogue = +bias -> out (fp32)
// ---------------------------------------------------------------------------
#define TK 64
#define NITER (KDIM / TK)        // 32
#define ROWB 144                 // smem row stride bytes (64 bf16 + pad)
#define TILE_B (128 * ROWB)      // 18432
#define BUF_B (4 * TILE_B)       // 73728
#define GEMM_SMEM (2 * BUF_B)    // 147456

__device__ __forceinline__ void stage_load(
    u32 sbuf, const __nv_bfloat16* __restrict__ Ahi,
    const __nv_bfloat16* __restrict__ Alo,
    const __nv_bfloat16* __restrict__ Bhi,
    const __nv_bfloat16* __restrict__ Blo,
    int rowBase, int colBase, int k0, int tid)
{
#pragma unroll
    for (int i = 0; i < 16; ++i) {
        const int tile = i >> 2;
        const int row  = (i & 3) * 32 + (tid >> 3);
        const int ch   = tid & 7;
        const __nv_bfloat16* srcb =
            (tile == 0) ? Ahi : (tile == 1) ? Alo : (tile == 2) ? Bhi : Blo;
        const int gr = ((tile < 2) ? rowBase : colBase) + row;
        const __nv_bfloat16* g = srcb + (size_t)gr * KDIM + k0 + ch * 8;
        const u32 dst = sbuf + tile * TILE_B + row * ROWB + ch * 16;
        CP_ASYNC16(dst, g);
    }
}

__global__ void __launch_bounds__(256, 1)
hmma_gemm_kernel(const float* __restrict__ cosb, const float* __restrict__ sinb,
                 const float* __restrict__ bias, float* __restrict__ out, int mode)
{
    extern __shared__ char smc[];
    const u32 smu = s2u(smc);
    const int tid  = threadIdx.x;
    const int lane = tid & 31;
    const int wid  = tid >> 5;
    const int warpM = wid & 3;
    const int warpN = wid >> 2;

    const __nv_bfloat16 *Ahi, *Alo, *Bhi, *Blo;
    if (mode == 0) { Ahi = gx_hi; Alo = gx_lo; Bhi = gw1_hi; Blo = gw1_lo; }
    else           { Ahi = ga_hi; Alo = ga_lo; Bhi = gw2_hi; Blo = gw2_lo; }

    const int rowBase = blockIdx.y * 128;
    const int colBase = blockIdx.x * 128;

    float acc[2][8][4];
#pragma unroll
    for (int mf = 0; mf < 2; ++mf)
#pragma unroll
        for (int nf = 0; nf < 8; ++nf)
#pragma unroll
            for (int r = 0; r < 4; ++r) acc[mf][nf][r] = 0.f;

    const int arow = warpM * 32 + (lane & 15);
    const u32 aoff = arow * ROWB + ((lane >> 4) * 8) * 2;
    const int brow = warpN * 64 + ((lane >> 4) << 3) + (lane & 7);
    const u32 boff = brow * ROWB + (((lane >> 3) & 1) * 8) * 2;

    stage_load(smu, Ahi, Alo, Bhi, Blo, rowBase, colBase, 0, tid);
    CP_COMMIT();

    for (int it = 0; it < NITER; ++it) {
        if (it + 1 < NITER)
            stage_load(smu + ((it + 1) & 1) * BUF_B, Ahi, Alo, Bhi, Blo,
                       rowBase, colBase, (it + 1) * TK, tid);
        CP_COMMIT();
        CP_WAIT1();
        __syncthreads();

        const u32 ab = smu + (it & 1) * BUF_B;
#pragma unroll
        for (int ks = 0; ks < 4; ++ks) {
            const u32 kb = ks * 32;
            u32 a_hi[8], a_lo[8], b_hi[16], b_lo[16];
#pragma unroll
            for (int mf = 0; mf < 2; ++mf) {
                LDSM4(&a_hi[mf * 4], ab + 0 * TILE_B + aoff + mf * 16 * ROWB + kb);
                LDSM4(&a_lo[mf * 4], ab + 1 * TILE_B + aoff + mf * 16 * ROWB + kb);
            }
#pragma unroll
            for (int np = 0; np < 4; ++np) {
                LDSM4(&b_hi[np * 4], ab + 2 * TILE_B + boff + np * 16 * ROWB + kb);
                LDSM4(&b_lo[np * 4], ab + 3 * TILE_B + boff + np * 16 * ROWB + kb);
            }
#pragma unroll
            for (int nf = 0; nf < 8; ++nf)
#pragma unroll
                for (int mf = 0; mf < 2; ++mf) {
                    MMA_BF16(acc[mf][nf], &a_hi[mf * 4], &b_hi[nf * 2]);
                    MMA_BF16(acc[mf][nf], &a_hi[mf * 4], &b_lo[nf * 2]);
                    MMA_BF16(acc[mf][nf], &a_lo[mf * 4], &b_hi[nf * 2]);
                }
        }
        __syncthreads();
    }

    // Epilogue. acc regs: c0,c1 -> row r cols c,c+1 ; c2,c3 -> row r+8.
    const int lane4 = lane >> 2;
    const int lanec = (lane & 3) * 2;

#pragma unroll
    for (int mf = 0; mf < 2; ++mf)
#pragma unroll
        for (int half = 0; half < 2; ++half) {
            const int m = rowBase + warpM * 32 + mf * 16 + lane4 + half * 8;
            if (mode == 0) {
                const int b = m >> 11;
                const int t = m & 2047;
#pragma unroll
                for (int nf = 0; nf < 8; ++nf) {
                    const int col = colBase + warpN * 64 + nf * 8 + lanec;
                    const float e = acc[mf][nf][half * 2 + 0];
                    const float o = acc[mf][nf][half * 2 + 1];
                    const int s = col >> 11;
                    const int h = (col >> 7) & 15;
                    const int d = col & 127;
                    __nv_bfloat16 *dh, *dl;
                    if      (s == 0) { dh = gq_hi; dl = gq_lo; }
                    else if (s == 1) { dh = gk_hi; dl = gk_lo; }
                    else             { dh = gv_hi; dl = gv_lo; }
                    const size_t base =
                        (((size_t)(b * NH_ + h)) * T_ + t) * HD_ + d;
                    float r0, r1;
                    if (s == 2) {
                        r0 = e; r1 = o;
                    } else {
                        const int i0 = d >> 1;
                        const float c  = cosb[t * 64 + i0];
                        const float sn = sinb[t * 64 + i0];
                        r0 = e * c - o * sn;
                        r1 = e * sn + o * c;
                    }
                    u32 lo2;
                    const u32 hi2 = pack_hl(r0, r1, lo2);
                    *reinterpret_cast<u32*>(dh + base) = hi2;
                    *reinterpret_cast<u32*>(dl + base) = lo2;
                }
            } else {
#pragma unroll
                for (int nf = 0; nf < 8; ++nf) {
                    const int col = colBase + warpN * 64 + nf * 8 + lanec;
                    float2 o2;
                    o2.x = acc[mf][nf][half * 2 + 0] + bias[col];
                    o2.y = acc[mf][nf][half * 2 + 1] + bias[col + 1];
                    *reinterpret_cast<float2*>(out + (size_t)m * HID_ + col) = o2;
                }
            }
        }
}

// ---------------------------------------------------------------------------
// Kernel 2: HMMA flash attention (bf16x3). CTA = 128 q rows of one (b,h).
// 8 warps, warp tile M16 x N64 (QK) / M16 x N128 (PV). KV chunks of 64,
// cp.async double-buffered. P converted to A-frags register-locally.
// ---------------------------------------------------------------------------
#define AROWB 272                    // 128 bf16 = 256B + 16 pad
#define QTILE (128 * AROWB)          // 34816
#define KVTILE (64 * AROWB)          // 17408
#define STAGE_B (4 * KVTILE)         // 69632: Khi,Klo,Vhi,Vlo
#define SM_KV (2 * QTILE)
#define ATTN_SMEM (2 * QTILE + 2 * STAGE_B)   // 208896

__device__ __forceinline__ void attn_stage_kv(
    u32 kvb, const __nv_bfloat16* __restrict__ Kh,
    const __nv_bfloat16* __restrict__ Kl,
    const __nv_bfloat16* __restrict__ Vh,
    const __nv_bfloat16* __restrict__ Vl,
    int n0, int tid)
{
#pragma unroll
    for (int i = 0; i < 16; ++i) {
        const int tile = i >> 2;                     // Khi,Klo,Vhi,Vlo
        const int idx  = (i & 3) * 256 + tid;        // 0..1023
        const int row  = idx >> 4;
        const int ch   = idx & 15;
        const __nv_bfloat16* srcb =
            (tile == 0) ? Kh : (tile == 1) ? Kl : (tile == 2) ? Vh : Vl;
        const __nv_bfloat16* g = srcb + (size_t)(n0 + row) * HD_ + ch * 8;
        const u32 dst = kvb + tile * KVTILE + row * AROWB + ch * 16;
        CP_ASYNC16(dst, g);
    }
}

__global__ void __launch_bounds__(256, 1) attn_hmma_kernel()
{
    extern __shared__ char smc[];
    const u32 smu = s2u(smc);
    const int tid  = threadIdx.x;
    const int lane = tid & 31;
    const int warp = tid >> 5;

    const int bh    = blockIdx.y;
    const int qBase = blockIdx.x * 128;
    const size_t bho = (size_t)bh * T_ * HD_;

    const __nv_bfloat16 *Qh = gq_hi + bho, *Ql = gq_lo + bho;
    const __nv_bfloat16 *Kh = gk_hi + bho, *Kl = gk_lo + bho;
    const __nv_bfloat16 *Vh = gv_hi + bho, *Vl = gv_lo + bho;

    // Load Q tiles (hi, lo): 2048 16B-chunks per tile
#pragma unroll
    for (int i = 0; i < 16; ++i) {
        const int tile = i >> 3;
        const int idx  = (i & 7) * 256 + tid;
        const int row  = idx >> 4;
        const int ch   = idx & 15;
        const __nv_bfloat16* g = (tile ? Ql : Qh) + (size_t)(qBase + row) * HD_ + ch * 8;
        CP_ASYNC16(smu + tile * QTILE + row * AROWB + ch * 16, g);
    }
    attn_stage_kv(smu + SM_KV, Kh, Kl, Vh, Vl, 0, tid);
    CP_COMMIT();

    // Per-thread softmax state (2 rows: r and r+8) + O accumulator
    float m0 = -1e30f, m1 = -1e30f, l0 = 0.f, l1 = 0.f;
    float oacc[16][4];
#pragma unroll
    for (int i = 0; i < 16; ++i)
#pragma unroll
        for (int j = 0; j < 4; ++j) oacc[i][j] = 0.f;

    const u32 aoff = (warp * 16 + (lane & 15)) * AROWB + (lane >> 4) * 16;
    const u32 boff = (((lane >> 4) << 3) + (lane & 7)) * AROWB + ((lane >> 3) & 1) * 16;
    // V trans-ldmatrix lane addressing
    const int vt = lane >> 3;
    const u32 voff = ((vt & 1) * 8 + (lane & 7)) * AROWB + ((vt >> 1) * 8) * 2;

    const float scale = 0.08838834764831845f;  // 1/sqrt(128)

    for (int it = 0; it < 32; ++it) {
        if (it + 1 < 32)
            attn_stage_kv(smu + SM_KV + ((it + 1) & 1) * STAGE_B,
                          Kh, Kl, Vh, Vl, (it + 1) * 64, tid);
        CP_COMMIT();
        CP_WAIT1();
        __syncthreads();

        const u32 kvb = smu + SM_KV + (it & 1) * STAGE_B;

        // ---- S = Q K^T (bf16x3) ----
        float sacc[8][4];
#pragma unroll
        for (int nf = 0; nf < 8; ++nf)
#pragma unroll
            for (int r = 0; r < 4; ++r) sacc[nf][r] = 0.f;

#pragma unroll
        for (int ks = 0; ks < 8; ++ks) {
            const u32 kb = ks * 32;
            u32 a_h[4], a_l[4], b_h[16], b_l[16];
            LDSM4(a_h, smu + aoff + kb);
            LDSM4(a_l, smu + QTILE + aoff + kb);
#pragma unroll
            for (int np = 0; np < 4; ++np) {
                LDSM4(&b_h[np * 4], kvb + 0 * KVTILE + boff + np * 16 * AROWB + kb);
                LDSM4(&b_l[np * 4], kvb + 1 * KVTILE + boff + np * 16 * AROWB + kb);
            }
#pragma unroll
            for (int nf = 0; nf < 8; ++nf) {
                MMA_BF16(sacc[nf], a_h, &b_h[nf * 2]);
                MMA_BF16(sacc[nf], a_h, &b_l[nf * 2]);
                MMA_BF16(sacc[nf], a_l, &b_h[nf * 2]);
            }
        }

        // ---- online softmax (rows r=lane>>2 and r+8) ----
        float mn0 = m0, mn1 = m1;
#pragma unroll
        for (int nf = 0; nf < 8; ++nf) {
#pragma unroll
            for (int r = 0; r < 4; ++r) sacc[nf][r] *= scale;
            mn0 = fmaxf(mn0, fmaxf(sacc[nf][0], sacc[nf][1]));
            mn1 = fmaxf(mn1, fmaxf(sacc[nf][2], sacc[nf][3]));
        }
        mn0 = fmaxf(mn0, __shfl_xor_sync(0xFFFFFFFFu, mn0, 1));
        mn0 = fmaxf(mn0, __shfl_xor_sync(0xFFFFFFFFu, mn0, 2));
        mn1 = fmaxf(mn1, __shfl_xor_sync(0xFFFFFFFFu, mn1, 1));
        mn1 = fmaxf(mn1, __shfl_xor_sync(0xFFFFFFFFu, mn1, 2));

        const float alpha0 = __expf(m0 - mn0);
        const float alpha1 = __expf(m1 - mn1);
        m0 = mn0; m1 = mn1;

        float s0 = 0.f, s1 = 0.f;
#pragma unroll
        for (int nf = 0; nf < 8; ++nf) {
            sacc[nf][0] = __expf(sacc[nf][0] - mn0);
            sacc[nf][1] = __expf(sacc[nf][1] - mn0);
            sacc[nf][2] = __expf(sacc[nf][2] - mn1);
            sacc[nf][3] = __expf(sacc[nf][3] - mn1);
            s0 += sacc[nf][0] + sacc[nf][1];
            s1 += sacc[nf][2] + sacc[nf][3];
        }
        s0 += __shfl_xor_sync(0xFFFFFFFFu, s0, 1);
        s0 += __shfl_xor_sync(0xFFFFFFFFu, s0, 2);
        s1 += __shfl_xor_sync(0xFFFFFFFFu, s1, 1);
        s1 += __shfl_xor_sync(0xFFFFFFFFu, s1, 2);
        l0 = l0 * alpha0 + s0;
        l1 = l1 * alpha1 + s1;

#pragma unroll
        for (int i = 0; i < 16; ++i) {
            oacc[i][0] *= alpha0;
            oacc[i][1] *= alpha0;
            oacc[i][2] *= alpha1;
            oacc[i][3] *= alpha1;
        }

        // ---- O += P V (bf16x3); P -> A-frags register-locally ----
#pragma unroll
        for (int ks2 = 0; ks2 < 4; ++ks2) {
            u32 p_h[4], p_l[4];
            p_h[0] = pack_hl(sacc[2 * ks2][0],     sacc[2 * ks2][1],     p_l[0]);
            p_h[1] = pack_hl(sacc[2 * ks2][2],     sacc[2 * ks2][3],     p_l[1]);
            p_h[2] = pack_hl(sacc[2 * ks2 + 1][0], sacc[2 * ks2 + 1][1], p_l[2]);
            p_h[3] = pack_hl(sacc[2 * ks2 + 1][2], sacc[2 * ks2 + 1][3], p_l[3]);
#pragma unroll
            for (int np2 = 0; np2 < 8; ++np2) {
                const u32 va = kvb + 2 * KVTILE + voff + (ks2 * 16) * AROWB + (np2 * 16) * 2;
                u32 v_h[4], v_l[4];
                LDSM4T(v_h, va);
                LDSM4T(v_l, va + KVTILE);
                MMA_BF16(oacc[np2 * 2 + 0], p_h, &v_h[0]);
                MMA_BF16(oacc[np2 * 2 + 1], p_h, &v_h[2]);
                MMA_BF16(oacc[np2 * 2 + 0], p_h, &v_l[0]);
                MMA_BF16(oacc[np2 * 2 + 1], p_h, &v_l[2]);
                MMA_BF16(oacc[np2 * 2 + 0], p_l, &v_h[0]);
                MMA_BF16(oacc[np2 * 2 + 1], p_l, &v_h[2]);
            }
        }
        __syncthreads();
    }

    // ---- epilogue: O /= l, split hi/lo -> ga ----
    const float inv0 = 1.f / l0;
    const float inv1 = 1.f / l1;
    const int b = bh >> 4;
    const int h = bh & 15;
    const int t0 = qBase + warp * 16 + (lane >> 2);
    const int t1 = t0 + 8;
    const size_t mrow0 = (size_t)(b * T_ + t0) * HID_ + h * HD_;
    const size_t mrow1 = (size_t)(b * T_ + t1) * HID_ + h * HD_;
    const int lanec = (lane & 3) * 2;

#pragma unroll
    for (int nf2 = 0; nf2 < 16; ++nf2) {
        const int col = nf2 * 8 + lanec;
        u32 lo2;
        u32 hi2 = pack_hl(oacc[nf2][0] * inv0, oacc[nf2][1] * inv0, lo2);
        *reinterpret_cast<u32*>(ga_hi + mrow0 + col) = hi2;
        *reinterpret_cast<u32*>(ga_lo + mrow0 + col) = lo2;
        hi2 = pack_hl(oacc[nf2][2] * inv1, oacc[nf2][3] * inv1, lo2);
        *reinterpret_cast<u32*>(ga_hi + mrow1 + col) = hi2;
        *reinterpret_cast<u32*>(ga_lo + mrow1 + col) = lo2;
    }
}

// ---------------------------------------------------------------------------
extern "C" void kernel_launch(void* const* d_in, const int* in_sizes, int n_in,
                              void* d_out, int out_size)
{
    const float* x      = (const float*)d_in[0];
    const float* w_qkv  = (const float*)d_in[1];
    const float* w_proj = (const float*)d_in[2];
    const float* b_proj = (const float*)d_in[3];
    const float* cosb   = (const float*)d_in[4];
    const float* sinb   = (const float*)d_in[5];
    float* out = (float*)d_out;

    cudaFuncSetAttribute(hmma_gemm_kernel, cudaFuncAttributeMaxDynamicSharedMemorySize,
                         GEMM_SMEM);
    cudaFuncSetAttribute(attn_hmma_kernel, cudaFuncAttributeMaxDynamicSharedMemorySize,
                         ATTN_SMEM);

    // 1) bf16 hi/lo splits of x, w_qkv, w_proj
    split_kernel<<<(M_ * HID_ / 4 + 255) / 256, 256>>>(x, 0, M_ * HID_ / 4);
    split_kernel<<<(NQKV_ * HID_ / 4 + 255) / 256, 256>>>(w_qkv, 1, NQKV_ * HID_ / 4);
    split_kernel<<<(HID_ * HID_ / 4 + 255) / 256, 256>>>(w_proj, 2, HID_ * HID_ / 4);

    // 2) QKV projection (HMMA bf16x3) + fused RoPE + hi/lo split scatter
    hmma_gemm_kernel<<<dim3(NQKV_ / 128, M_ / 128), 256, GEMM_SMEM>>>(
        cosb, sinb, nullptr, nullptr, 0);

    // 3) Flash attention (HMMA bf16x3), writes ga_hi/ga_lo directly
    attn_hmma_kernel<<<dim3(T_ / 128, B_ * NH_), 256, ATTN_SMEM>>>();

    // 4) Output projection (HMMA bf16x3) + bias
    hmma_gemm_kernel<<<dim3(HID_ / 128, M_ / 128), 256, GEMM_SMEM>>>(
        nullptr, nullptr, b_proj, out, 1);
}

// round 17
// speedup vs baseline: 5.5128x; 1.0156x over previous
#include <cuda_runtime.h>
#include <cuda_bf16.h>

typedef unsigned int u32;
typedef unsigned long long u64;

// Problem constants
#define B_    4
#define T_    2048
#define HID_  2048
#define NH_   16
#define HD_   128
#define M_    (B_ * T_)       // 8192
#define NQKV_ (3 * HID_)      // 6144
#define KDIM  2048

// ---------------------------------------------------------------------------
// Scratch (device globals; no allocations allowed)
// ---------------------------------------------------------------------------
__device__ __nv_bfloat16 gx_hi[16777216],  gx_lo[16777216];   // x split
__device__ __nv_bfloat16 gw1_hi[12582912], gw1_lo[12582912];  // w_qkv split
__device__ __nv_bfloat16 gw2_hi[4194304],  gw2_lo[4194304];   // w_proj split
__device__ __nv_bfloat16 ga_hi[16777216],  ga_lo[16777216];   // attn out split
__device__ __nv_bfloat16 gq_hi[16777216],  gq_lo[16777216];   // q (RoPE'd) split
__device__ __nv_bfloat16 gk_hi[16777216],  gk_lo[16777216];   // k (RoPE'd) split
__device__ __nv_bfloat16 gv_hi[16777216],  gv_lo[16777216];   // v split

// ---------------------------------------------------------------------------
// PTX helpers — BASE-target only (no 'a'-suffix features; ptxas targets sm_103)
// ---------------------------------------------------------------------------
__device__ __forceinline__ u32 s2u(const void* p) {
    u32 a;
    asm("{ .reg .u64 t; cvta.to.shared.u64 t, %1; cvt.u32.u64 %0, t; }"
        : "=r"(a) : "l"(p));
    return a;
}

#define CP_ASYNC16(dst, src) \
    asm volatile("cp.async.cg.shared.global [%0], [%1], 16;" \
                 :: "r"(dst), "l"(src) : "memory")
#define CP_COMMIT() asm volatile("cp.async.commit_group;" ::: "memory")
#define CP_WAITG1() asm volatile("cp.async.wait_group 1;" ::: "memory")

#define LDSM4(R, addr) \
    asm volatile("ldmatrix.sync.aligned.m8n8.x4.shared.b16 {%0,%1,%2,%3}, [%4];" \
        : "=r"((R)[0]), "=r"((R)[1]), "=r"((R)[2]), "=r"((R)[3]) : "r"(addr))

#define LDSM4T(R, addr) \
    asm volatile("ldmatrix.sync.aligned.m8n8.x4.trans.shared.b16 {%0,%1,%2,%3}, [%4];" \
        : "=r"((R)[0]), "=r"((R)[1]), "=r"((R)[2]), "=r"((R)[3]) : "r"(addr))

#define MMA_BF16(c, a, b) \
    asm volatile("mma.sync.aligned.m16n8k16.row.col.f32.bf16.bf16.f32 " \
        "{%0,%1,%2,%3}, {%4,%5,%6,%7}, {%8,%9}, {%0,%1,%2,%3};" \
        : "+f"((c)[0]), "+f"((c)[1]), "+f"((c)[2]), "+f"((c)[3]) \
        : "r"((a)[0]), "r"((a)[1]), "r"((a)[2]), "r"((a)[3]), \
          "r"((b)[0]), "r"((b)[1]))

__device__ __forceinline__ u32 pack_hl(float a, float b, u32& lo_out) {
    const __nv_bfloat16 ha = __float2bfloat16(a);
    const __nv_bfloat16 hb = __float2bfloat16(b);
    const __nv_bfloat16 la = __float2bfloat16(a - __bfloat162float(ha));
    const __nv_bfloat16 lb = __float2bfloat16(b - __bfloat162float(hb));
    __nv_bfloat162 H; H.x = ha; H.y = hb;
    __nv_bfloat162 L; L.x = la; L.y = lb;
    lo_out = *reinterpret_cast<u32*>(&L);
    return *reinterpret_cast<u32*>(&H);
}

// ---------------------------------------------------------------------------
// Kernel: fp32 -> bf16 hi/lo split. which: 0=x, 1=w_qkv, 2=w_proj
// ---------------------------------------------------------------------------
__global__ void split_kernel(const float* __restrict__ src, int which, int n4)
{
    const int i = blockIdx.x * blockDim.x + threadIdx.x;
    if (i >= n4) return;
    __nv_bfloat16 *hi, *lo;
    if      (which == 0) { hi = gx_hi;  lo = gx_lo;  }
    else if (which == 1) { hi = gw1_hi; lo = gw1_lo; }
    else                 { hi = gw2_hi; lo = gw2_lo; }

    const float4 v = reinterpret_cast<const float4*>(src)[i];
    u32 l01, l23;
    const u32 h01 = pack_hl(v.x, v.y, l01);
    const u32 h23 = pack_hl(v.z, v.w, l23);
    reinterpret_cast<u32*>(hi)[2 * i + 0] = h01;
    reinterpret_cast<u32*>(hi)[2 * i + 1] = h23;
    reinterpret_cast<u32*>(lo)[2 * i + 0] = l01;
    reinterpret_cast<u32*>(lo)[2 * i + 1] = l23;
}

// ---------------------------------------------------------------------------
// HMMA GEMM: C[128,128 tile] = A[M,K] * B[N,K]^T with bf16x3 compensation.
// 3-stage cp.async pipeline, ONE __syncthreads per K-chunk.
// mode 0: A=x split, B=w_qkv split, epilogue = RoPE + hi/lo split scatter
// mode 1: A=attn split, B=w_proj split, epilogue = +bias -> out (fp32)
// ---------------------------------------------------------------------------
#define TK 64
#define NITER (KDIM / TK)        // 32
#define ROWB 144                 // smem row stride bytes (64 bf16 + pad)
#define TILE_B (128 * ROWB)      // 18432
#define BUF_B (4 * TILE_B)       // 73728
#define GEMM_SMEM (3 * BUF_B)    // 221184 (3-stage)

__device__ __forceinline__ void stage_load(
    u32 sbuf, const __nv_bfloat16* __restrict__ Ahi,
    const __nv_bfloat16* __restrict__ Alo,
    const __nv_bfloat16* __restrict__ Bhi,
    const __nv_bfloat16* __restrict__ Blo,
    int rowBase, int colBase, int k0, int tid)
{
#pragma unroll
    for (int i = 0; i < 16; ++i) {
        const int tile = i >> 2;
        const int row  = (i & 3) * 32 + (tid >> 3);
        const int ch   = tid & 7;
        const __nv_bfloat16* srcb =
            (tile == 0) ? Ahi : (tile == 1) ? Alo : (tile == 2) ? Bhi : Blo;
        const int gr = ((tile < 2) ? rowBase : colBase) + row;
        const __nv_bfloat16* g = srcb + (size_t)gr * KDIM + k0 + ch * 8;
        const u32 dst = sbuf + tile * TILE_B + row * ROWB + ch * 16;
        CP_ASYNC16(dst, g);
    }
}

__global__ void __launch_bounds__(256, 1)
hmma_gemm_kernel(const float* __restrict__ cosb, const float* __restrict__ sinb,
                 const float* __restrict__ bias, float* __restrict__ out, int mode)
{
    extern __shared__ char smc[];
    const u32 smu = s2u(smc);
    const int tid  = threadIdx.x;
    const int lane = tid & 31;
    const int wid  = tid >> 5;
    const int warpM = wid & 3;
    const int warpN = wid >> 2;

    const __nv_bfloat16 *Ahi, *Alo, *Bhi, *Blo;
    if (mode == 0) { Ahi = gx_hi; Alo = gx_lo; Bhi = gw1_hi; Blo = gw1_lo; }
    else           { Ahi = ga_hi; Alo = ga_lo; Bhi = gw2_hi; Blo = gw2_lo; }

    const int rowBase = blockIdx.y * 128;
    const int colBase = blockIdx.x * 128;

    float acc[2][8][4];
#pragma unroll
    for (int mf = 0; mf < 2; ++mf)
#pragma unroll
        for (int nf = 0; nf < 8; ++nf)
#pragma unroll
            for (int r = 0; r < 4; ++r) acc[mf][nf][r] = 0.f;

    const int arow = warpM * 32 + (lane & 15);
    const u32 aoff = arow * ROWB + ((lane >> 4) * 8) * 2;
    const int brow = warpN * 64 + ((lane >> 4) << 3) + (lane & 7);
    const u32 boff = brow * ROWB + (((lane >> 3) & 1) * 8) * 2;

    // Prologue: stage chunks 0 and 1
    stage_load(smu + 0 * BUF_B, Ahi, Alo, Bhi, Blo, rowBase, colBase, 0, tid);
    CP_COMMIT();
    stage_load(smu + 1 * BUF_B, Ahi, Alo, Bhi, Blo, rowBase, colBase, TK, tid);
    CP_COMMIT();

    int bufc = 0;   // (it % 3)
    int bufn = 2;   // ((it+2) % 3)
    for (int it = 0; it < NITER; ++it) {
        CP_WAITG1();          // chunk `it` resident (chunk it+1 may be in flight)
        __syncthreads();      // all threads done with compute(it-1); chunk it visible

        if (it + 2 < NITER)
            stage_load(smu + bufn * BUF_B, Ahi, Alo, Bhi, Blo,
                       rowBase, colBase, (it + 2) * TK, tid);
        CP_COMMIT();          // always commit (empty groups keep counts aligned)

        const u32 ab = smu + bufc * BUF_B;
#pragma unroll
        for (int ks = 0; ks < 4; ++ks) {
            const u32 kb = ks * 32;
            u32 a_hi[8], a_lo[8], b_hi[16], b_lo[16];
#pragma unroll
            for (int mf = 0; mf < 2; ++mf) {
                LDSM4(&a_hi[mf * 4], ab + 0 * TILE_B + aoff + mf * 16 * ROWB + kb);
                LDSM4(&a_lo[mf * 4], ab + 1 * TILE_B + aoff + mf * 16 * ROWB + kb);
            }
#pragma unroll
            for (int np = 0; np < 4; ++np) {
                LDSM4(&b_hi[np * 4], ab + 2 * TILE_B + boff + np * 16 * ROWB + kb);
                LDSM4(&b_lo[np * 4], ab + 3 * TILE_B + boff + np * 16 * ROWB + kb);
            }
#pragma unroll
            for (int nf = 0; nf < 8; ++nf)
#pragma unroll
                for (int mf = 0; mf < 2; ++mf) {
                    MMA_BF16(acc[mf][nf], &a_hi[mf * 4], &b_hi[nf * 2]);
                    MMA_BF16(acc[mf][nf], &a_hi[mf * 4], &b_lo[nf * 2]);
                    MMA_BF16(acc[mf][nf], &a_lo[mf * 4], &b_hi[nf * 2]);
                }
        }
        bufc = (bufc == 2) ? 0 : bufc + 1;
        bufn = (bufn == 2) ? 0 : bufn + 1;
    }

    // Epilogue. acc regs: c0,c1 -> row r cols c,c+1 ; c2,c3 -> row r+8.
    const int lane4 = lane >> 2;
    const int lanec = (lane & 3) * 2;

#pragma unroll
    for (int mf = 0; mf < 2; ++mf)
#pragma unroll
        for (int half = 0; half < 2; ++half) {
            const int m = rowBase + warpM * 32 + mf * 16 + lane4 + half * 8;
            if (mode == 0) {
                const int b = m >> 11;
                const int t = m & 2047;
#pragma unroll
                for (int nf = 0; nf < 8; ++nf) {
                    const int col = colBase + warpN * 64 + nf * 8 + lanec;
                    const float e = acc[mf][nf][half * 2 + 0];
                    const float o = acc[mf][nf][half * 2 + 1];
                    const int s = col >> 11;
                    const int h = (col >> 7) & 15;
                    const int d = col & 127;
                    __nv_bfloat16 *dh, *dl;
                    if      (s == 0) { dh = gq_hi; dl = gq_lo; }
                    else if (s == 1) { dh = gk_hi; dl = gk_lo; }
                    else             { dh = gv_hi; dl = gv_lo; }
                    const size_t base =
                        (((size_t)(b * NH_ + h)) * T_ + t) * HD_ + d;
                    float r0, r1;
                    if (s == 2) {
                        r0 = e; r1 = o;
                    } else {
                        const int i0 = d >> 1;
                        const float c  = cosb[t * 64 + i0];
                        const float sn = sinb[t * 64 + i0];
                        r0 = e * c - o * sn;
                        r1 = e * sn + o * c;
                    }
                    u32 lo2;
                    const u32 hi2 = pack_hl(r0, r1, lo2);
                    *reinterpret_cast<u32*>(dh + base) = hi2;
                    *reinterpret_cast<u32*>(dl + base) = lo2;
                }
            } else {
#pragma unroll
                for (int nf = 0; nf < 8; ++nf) {
                    const int col = colBase + warpN * 64 + nf * 8 + lanec;
                    float2 o2;
                    o2.x = acc[mf][nf][half * 2 + 0] + bias[col];
                    o2.y = acc[mf][nf][half * 2 + 1] + bias[col + 1];
                    *reinterpret_cast<float2*>(out + (size_t)m * HID_ + col) = o2;
                }
            }
        }
}

// ---------------------------------------------------------------------------
// Kernel 2: HMMA flash attention (bf16x3). CTA = 128 q rows of one (b,h).
// 8 warps, warp tile M16 x N64 (QK) / M16 x N128 (PV). KV chunks of 64,
// cp.async double-buffered. P converted to A-frags register-locally.
// ---------------------------------------------------------------------------
#define AROWB 272                    // 128 bf16 = 256B + 16 pad
#define QTILE (128 * AROWB)          // 34816
#define KVTILE (64 * AROWB)          // 17408
#define STAGE_B (4 * KVTILE)         // 69632: Khi,Klo,Vhi,Vlo
#define SM_KV (2 * QTILE)
#define ATTN_SMEM (2 * QTILE + 2 * STAGE_B)   // 208896

__device__ __forceinline__ void attn_stage_kv(
    u32 kvb, const __nv_bfloat16* __restrict__ Kh,
    const __nv_bfloat16* __restrict__ Kl,
    const __nv_bfloat16* __restrict__ Vh,
    const __nv_bfloat16* __restrict__ Vl,
    int n0, int tid)
{
#pragma unroll
    for (int i = 0; i < 16; ++i) {
        const int tile = i >> 2;                     // Khi,Klo,Vhi,Vlo
        const int idx  = (i & 3) * 256 + tid;        // 0..1023
        const int row  = idx >> 4;
        const int ch   = idx & 15;
        const __nv_bfloat16* srcb =
            (tile == 0) ? Kh : (tile == 1) ? Kl : (tile == 2) ? Vh : Vl;
        const __nv_bfloat16* g = srcb + (size_t)(n0 + row) * HD_ + ch * 8;
        const u32 dst = kvb + tile * KVTILE + row * AROWB + ch * 16;
        CP_ASYNC16(dst, g);
    }
}

__global__ void __launch_bounds__(256, 1) attn_hmma_kernel()
{
    extern __shared__ char smc[];
    const u32 smu = s2u(smc);
    const int tid  = threadIdx.x;
    const int lane = tid & 31;
    const int warp = tid >> 5;

    const int bh    = blockIdx.y;
    const int qBase = blockIdx.x * 128;
    const size_t bho = (size_t)bh * T_ * HD_;

    const __nv_bfloat16 *Qh = gq_hi + bho, *Ql = gq_lo + bho;
    const __nv_bfloat16 *Kh = gk_hi + bho, *Kl = gk_lo + bho;
    const __nv_bfloat16 *Vh = gv_hi + bho, *Vl = gv_lo + bho;

    // Load Q tiles (hi, lo): 2048 16B-chunks per tile
#pragma unroll
    for (int i = 0; i < 16; ++i) {
        const int tile = i >> 3;
        const int idx  = (i & 7) * 256 + tid;
        const int row  = idx >> 4;
        const int ch   = idx & 15;
        const __nv_bfloat16* g = (tile ? Ql : Qh) + (size_t)(qBase + row) * HD_ + ch * 8;
        CP_ASYNC16(smu + tile * QTILE + row * AROWB + ch * 16, g);
    }
    attn_stage_kv(smu + SM_KV, Kh, Kl, Vh, Vl, 0, tid);
    CP_COMMIT();

    // Per-thread softmax state (2 rows: r and r+8) + O accumulator
    float m0 = -1e30f, m1 = -1e30f, l0 = 0.f, l1 = 0.f;
    float oacc[16][4];
#pragma unroll
    for (int i = 0; i < 16; ++i)
#pragma unroll
        for (int j = 0; j < 4; ++j) oacc[i][j] = 0.f;

    const u32 aoff = (warp * 16 + (lane & 15)) * AROWB + (lane >> 4) * 16;
    const u32 boff = (((lane >> 4) << 3) + (lane & 7)) * AROWB + ((lane >> 3) & 1) * 16;
    // V trans-ldmatrix lane addressing
    const int vt = lane >> 3;
    const u32 voff = ((vt & 1) * 8 + (lane & 7)) * AROWB + ((vt >> 1) * 8) * 2;

    const float scale = 0.08838834764831845f;  // 1/sqrt(128)

    for (int it = 0; it < 32; ++it) {
        if (it + 1 < 32)
            attn_stage_kv(smu + SM_KV + ((it + 1) & 1) * STAGE_B,
                          Kh, Kl, Vh, Vl, (it + 1) * 64, tid);
        CP_COMMIT();
        CP_WAITG1();
        __syncthreads();

        const u32 kvb = smu + SM_KV + (it & 1) * STAGE_B;

        // ---- S = Q K^T (bf16x3) ----
        float sacc[8][4];
#pragma unroll
        for (int nf = 0; nf < 8; ++nf)
#pragma unroll
            for (int r = 0; r < 4; ++r) sacc[nf][r] = 0.f;

#pragma unroll
        for (int ks = 0; ks < 8; ++ks) {
            const u32 kb = ks * 32;
            u32 a_h[4], a_l[4], b_h[16], b_l[16];
            LDSM4(a_h, smu + aoff + kb);
            LDSM4(a_l, smu + QTILE + aoff + kb);
#pragma unroll
            for (int np = 0; np < 4; ++np) {
                LDSM4(&b_h[np * 4], kvb + 0 * KVTILE + boff + np * 16 * AROWB + kb);
                LDSM4(&b_l[np * 4], kvb + 1 * KVTILE + boff + np * 16 * AROWB + kb);
            }
#pragma unroll
            for (int nf = 0; nf < 8; ++nf) {
                MMA_BF16(sacc[nf], a_h, &b_h[nf * 2]);
                MMA_BF16(sacc[nf], a_h, &b_l[nf * 2]);
                MMA_BF16(sacc[nf], a_l, &b_h[nf * 2]);
            }
        }

        // ---- online softmax (rows r=lane>>2 and r+8) ----
        float mn0 = m0, mn1 = m1;
#pragma unroll
        for (int nf = 0; nf < 8; ++nf) {
#pragma unroll
            for (int r = 0; r < 4; ++r) sacc[nf][r] *= scale;
            mn0 = fmaxf(mn0, fmaxf(sacc[nf][0], sacc[nf][1]));
            mn1 = fmaxf(mn1, fmaxf(sacc[nf][2], sacc[nf][3]));
        }
        mn0 = fmaxf(mn0, __shfl_xor_sync(0xFFFFFFFFu, mn0, 1));
        mn0 = fmaxf(mn0, __shfl_xor_sync(0xFFFFFFFFu, mn0, 2));
        mn1 = fmaxf(mn1, __shfl_xor_sync(0xFFFFFFFFu, mn1, 1));
        mn1 = fmaxf(mn1, __shfl_xor_sync(0xFFFFFFFFu, mn1, 2));

        const float alpha0 = __expf(m0 - mn0);
        const float alpha1 = __expf(m1 - mn1);
        m0 = mn0; m1 = mn1;

        float s0 = 0.f, s1 = 0.f;
#pragma unroll
        for (int nf = 0; nf < 8; ++nf) {
            sacc[nf][0] = __expf(sacc[nf][0] - mn0);
            sacc[nf][1] = __expf(sacc[nf][1] - mn0);
            sacc[nf][2] = __expf(sacc[nf][2] - mn1);
            sacc[nf][3] = __expf(sacc[nf][3] - mn1);
            s0 += sacc[nf][0] + sacc[nf][1];
            s1 += sacc[nf][2] + sacc[nf][3];
        }
        s0 += __shfl_xor_sync(0xFFFFFFFFu, s0, 1);
        s0 += __shfl_xor_sync(0xFFFFFFFFu, s0, 2);
        s1 += __shfl_xor_sync(0xFFFFFFFFu, s1, 1);
        s1 += __shfl_xor_sync(0xFFFFFFFFu, s1, 2);
        l0 = l0 * alpha0 + s0;
        l1 = l1 * alpha1 + s1;

#pragma unroll
        for (int i = 0; i < 16; ++i) {
            oacc[i][0] *= alpha0;
            oacc[i][1] *= alpha0;
            oacc[i][2] *= alpha1;
            oacc[i][3] *= alpha1;
        }

        // ---- O += P V (bf16x3); P -> A-frags register-locally ----
#pragma unroll
        for (int ks2 = 0; ks2 < 4; ++ks2) {
            u32 p_h[4], p_l[4];
            p_h[0] = pack_hl(sacc[2 * ks2][0],     sacc[2 * ks2][1],     p_l[0]);
            p_h[1] = pack_hl(sacc[2 * ks2][2],     sacc[2 * ks2][3],     p_l[1]);
            p_h[2] = pack_hl(sacc[2 * ks2 + 1][0], sacc[2 * ks2 + 1][1], p_l[2]);
            p_h[3] = pack_hl(sacc[2 * ks2 + 1][2], sacc[2 * ks2 + 1][3], p_l[3]);
#pragma unroll
            for (int np2 = 0; np2 < 8; ++np2) {
                const u32 va = kvb + 2 * KVTILE + voff + (ks2 * 16) * AROWB + (np2 * 16) * 2;
                u32 v_h[4], v_l[4];
                LDSM4T(v_h, va);
                LDSM4T(v_l, va + KVTILE);
                MMA_BF16(oacc[np2 * 2 + 0], p_h, &v_h[0]);
                MMA_BF16(oacc[np2 * 2 + 1], p_h, &v_h[2]);
                MMA_BF16(oacc[np2 * 2 + 0], p_h, &v_l[0]);
                MMA_BF16(oacc[np2 * 2 + 1], p_h, &v_l[2]);
                MMA_BF16(oacc[np2 * 2 + 0], p_l, &v_h[0]);
                MMA_BF16(oacc[np2 * 2 + 1], p_l, &v_h[2]);
            }
        }
        __syncthreads();
    }

    // ---- epilogue: O /= l, split hi/lo -> ga ----
    const float inv0 = 1.f / l0;
    const float inv1 = 1.f / l1;
    const int b = bh >> 4;
    const int h = bh & 15;
    const int t0 = qBase + warp * 16 + (lane >> 2);
    const int t1 = t0 + 8;
    const size_t mrow0 = (size_t)(b * T_ + t0) * HID_ + h * HD_;
    const size_t mrow1 = (size_t)(b * T_ + t1) * HID_ + h * HD_;
    const int lanec = (lane & 3) * 2;

#pragma unroll
    for (int nf2 = 0; nf2 < 16; ++nf2) {
        const int col = nf2 * 8 + lanec;
        u32 lo2;
        u32 hi2 = pack_hl(oacc[nf2][0] * inv0, oacc[nf2][1] * inv0, lo2);
        *reinterpret_cast<u32*>(ga_hi + mrow0 + col) = hi2;
        *reinterpret_cast<u32*>(ga_lo + mrow0 + col) = lo2;
        hi2 = pack_hl(oacc[nf2][2] * inv1, oacc[nf2][3] * inv1, lo2);
        *reinterpret_cast<u32*>(ga_hi + mrow1 + col) = hi2;
        *reinterpret_cast<u32*>(ga_lo + mrow1 + col) = lo2;
    }
}

// ---------------------------------------------------------------------------
extern "C" void kernel_launch(void* const* d_in, const int* in_sizes, int n_in,
                              void* d_out, int out_size)
{
    const float* x      = (const float*)d_in[0];
    const float* w_qkv  = (const float*)d_in[1];
    const float* w_proj = (const float*)d_in[2];
    const float* b_proj = (const float*)d_in[3];
    const float* cosb   = (const float*)d_in[4];
    const float* sinb   = (const float*)d_in[5];
    float* out = (float*)d_out;

    cudaFuncSetAttribute(hmma_gemm_kernel, cudaFuncAttributeMaxDynamicSharedMemorySize,
                         GEMM_SMEM);
    cudaFuncSetAttribute(attn_hmma_kernel, cudaFuncAttributeMaxDynamicSharedMemorySize,
                         ATTN_SMEM);

    // 1) bf16 hi/lo splits of x, w_qkv, w_proj
    split_kernel<<<(M_ * HID_ / 4 + 255) / 256, 256>>>(x, 0, M_ * HID_ / 4);
    split_kernel<<<(NQKV_ * HID_ / 4 + 255) / 256, 256>>>(w_qkv, 1, NQKV_ * HID_ / 4);
    split_kernel<<<(HID_ * HID_ / 4 + 255) / 256, 256>>>(w_proj, 2, HID_ * HID_ / 4);

    // 2) QKV projection (HMMA bf16x3) + fused RoPE + hi/lo split scatter
    hmma_gemm_kernel<<<dim3(NQKV_ / 128, M_ / 128), 256, GEMM_SMEM>>>(
        cosb, sinb, nullptr, nullptr, 0);

    // 3) Flash attention (HMMA bf16x3), writes ga_hi/ga_lo directly
    attn_hmma_kernel<<<dim3(T_ / 128, B_ * NH_), 256, ATTN_SMEM>>>();

    // 4) Output projection (HMMA bf16x3) + bias
    hmma_gemm_kernel<<<dim3(HID_ / 128, M_ / 128), 256, GEMM_SMEM>>>(
        nullptr, nullptr, b_proj, out, 1);
}